// round 8
// baseline (speedup 1.0000x reference)
#include <cuda_runtime.h>
#include <cuda_fp16.h>
#include <cstdint>

// ---------------- problem dims ----------------
#define MDIM 8192
#define NDIM 4096
#define KDIM 4096

// ---------------- GEMM tiling ----------------
#define BM 128
#define BN 128
#define BK 128                 // 128 s8 = 128 B per SMEM row (swizzle atom)
#define STAGES 4
#define KT_ITERS (KDIM / BK)   // 32
#define THREADS 256            // 8 warps: 2 (m) x 4 (n), warp tile 64x32

// SMEM per stage: A_hi 16KB | A_lo 16KB | B 16KB
#define OFF_AH 0
#define OFF_AL 16384
#define OFF_B  32768
#define STAGE_BYTES 49152
#define SMEM_TOTAL (STAGES * STAGE_BYTES)   // 196608 -> 1 CTA/SM

#define QUANT_BLOCKS MDIM                          // 8192, one block per row
#define UNPACK_BLOCKS (NDIM * (KDIM / 2) / 256)    // 32768

// ---------------- scratch (allocation-free __device__ globals) ----------------
__device__ signed char g_Ah[(size_t)MDIM * KDIM];  // 32 MB s8 activation hi
__device__ signed char g_Al[(size_t)MDIM * KDIM];  // 32 MB s8 activation lo
__device__ signed char g_Bw[(size_t)NDIM * KDIM];  // 16 MB s8 weights (exact int4)
__device__ float g_sx[MDIM];                       // per-row activation scales

// ---------------- PTX helpers ----------------
__device__ __forceinline__ uint32_t smem_u32(const void* p) {
    return (uint32_t)__cvta_generic_to_shared(p);
}
__device__ __forceinline__ void cp16(uint32_t s, const void* g) {
    asm volatile("cp.async.cg.shared.global [%0], [%1], 16;" :: "r"(s), "l"(g));
}
__device__ __forceinline__ void cp_commit() {
    asm volatile("cp.async.commit_group;" ::: "memory");
}
template <int N>
__device__ __forceinline__ void cp_wait() {
    asm volatile("cp.async.wait_group %0;" :: "n"(N) : "memory");
}
__device__ __forceinline__ void ldsm_x4(uint32_t* d, uint32_t addr) {
    asm volatile("ldmatrix.sync.aligned.m8n8.x4.shared.b16 {%0,%1,%2,%3}, [%4];"
                 : "=r"(d[0]), "=r"(d[1]), "=r"(d[2]), "=r"(d[3]) : "r"(addr));
}
__device__ __forceinline__ void imma16832(int* c, const uint32_t* a,
                                          uint32_t b0, uint32_t b1) {
    asm volatile(
        "mma.sync.aligned.m16n8k32.row.col.s32.s8.s8.s32 "
        "{%0,%1,%2,%3}, {%4,%5,%6,%7}, {%8,%9}, {%0,%1,%2,%3};"
        : "+r"(c[0]), "+r"(c[1]), "+r"(c[2]), "+r"(c[3])
        : "r"(a[0]), "r"(a[1]), "r"(a[2]), "r"(a[3]), "r"(b0), "r"(b1));
}

// ---------------- prep: per-row two-term int8 quant of x  +  weight unpack ----
// blocks [0, MDIM): one block per activation row
// blocks [MDIM, +UNPACK_BLOCKS): int4 -> exact s8 (XOR 0x88 + sext == nibble-8)
__global__ __launch_bounds__(256) void prep_kernel(const float* __restrict__ x,
                                                   const int* __restrict__ wp) {
    int bid = blockIdx.x;
    int tid = threadIdx.x;
    if (bid < QUANT_BLOCKS) {
        const float* row = x + (size_t)bid * KDIM;
        float v[16];
        float mx = 0.0f;
        #pragma unroll
        for (int j = 0; j < 16; j++) {
            v[j] = row[tid + j * 256];
            mx = fmaxf(mx, fabsf(v[j]));
        }
        #pragma unroll
        for (int off = 16; off; off >>= 1)
            mx = fmaxf(mx, __shfl_xor_sync(0xFFFFFFFF, mx, off));
        __shared__ float red[8];
        if ((tid & 31) == 0) red[tid >> 5] = mx;
        __syncthreads();
        mx = red[0];
        #pragma unroll
        for (int k = 1; k < 8; k++) mx = fmaxf(mx, red[k]);
        mx = fmaxf(mx, 1e-30f);

        const float s = mx * (1.0f / 127.0f);
        const float inv = 127.0f / mx;
        signed char* ah = g_Ah + (size_t)bid * KDIM;
        signed char* al = g_Al + (size_t)bid * KDIM;
        #pragma unroll
        for (int j = 0; j < 16; j++) {
            float h = rintf(v[j] * inv);                 // in [-127, 127]
            float r = v[j] - h * s;
            float l = rintf(r * inv * 256.0f);           // in [-128, 128]
            l = fminf(fmaxf(l, -127.0f), 127.0f);
            ah[tid + j * 256] = (signed char)(int)h;
            al[tid + j * 256] = (signed char)(int)l;
        }
        if (tid == 0) g_sx[bid] = s;
    } else {
        int idx = (bid - QUANT_BLOCKS) * 256 + tid;      // 0 .. N*K/2-1
        int v = wp[idx];
        int lo = (v & 0xF) - 8;
        int hi = ((v >> 4) & 0xF) - 8;
        // little-endian: low byte = even k, high byte = odd k
        reinterpret_cast<short*>(g_Bw)[idx] =
            (short)((lo & 0xFF) | (hi << 8));
    }
}

// ---------------- stage loader: 3 x 1024 chunks of 16B ----------------
__device__ __forceinline__ void load_stage(uint32_t sbase, int tid, int kt,
                                           int m0, int n0) {
    const char* gah = (const char*)(g_Ah + (size_t)m0 * KDIM + kt * BK);
    const char* gal = (const char*)(g_Al + (size_t)m0 * KDIM + kt * BK);
    const char* gb  = (const char*)(g_Bw + (size_t)n0 * KDIM + kt * BK);
    #pragma unroll
    for (int j = 0; j < 4; j++) {          // A_hi: 128 rows x 8 units
        int c = tid + j * THREADS;
        int row = c >> 3, u = c & 7;
        uint32_t sa = sbase + OFF_AH + row * 128 + (((uint32_t)(u ^ (row & 7))) << 4);
        cp16(sa, gah + (size_t)row * KDIM + u * 16);
    }
    #pragma unroll
    for (int j = 0; j < 4; j++) {          // A_lo
        int c = tid + j * THREADS;
        int row = c >> 3, u = c & 7;
        uint32_t sa = sbase + OFF_AL + row * 128 + (((uint32_t)(u ^ (row & 7))) << 4);
        cp16(sa, gal + (size_t)row * KDIM + u * 16);
    }
    #pragma unroll
    for (int j = 0; j < 4; j++) {          // B
        int c = tid + j * THREADS;
        int row = c >> 3, u = c & 7;
        uint32_t sa = sbase + OFF_B + row * 128 + (((uint32_t)(u ^ (row & 7))) << 4);
        cp16(sa, gb + (size_t)row * KDIM + u * 16);
    }
}

// ---------------- kernel: s8 split GEMM (hi + lo) + fused epilogue ----------------
__global__ __launch_bounds__(THREADS, 1) void gemm_kernel(
    const float* __restrict__ scales, const float* __restrict__ bias,
    float* __restrict__ out)
{
    extern __shared__ char smem[];
    const uint32_t sb = smem_u32(smem);
    const int tid = threadIdx.x;
    const int wid = tid >> 5;
    const int lane = tid & 31;

    const int tn = blockIdx.x & 31;   // 32 N-tiles (fastest -> A reuse in L2)
    const int tm = blockIdx.x >> 5;   // 64 M-tiles
    const int m0 = tm * BM;
    const int n0 = tn * BN;

    const int warp_m = wid & 1;       // 2 groups of 64 rows
    const int warp_n = wid >> 1;      // 4 groups of 32 cols

    // ldmatrix addressing: 16B units within 128B rows, swizzle u ^ (row & 7)
    // s8 k32 fragments map exactly like fp16 k16 (same 16B-unit tile pattern).
    const int a_row = warp_m * 64 + (lane & 15);
    const int a_u0  = lane >> 4;                         // + 2*ks
    const int b_row = warp_n * 32 + (lane & 7) + ((lane >> 4) << 3);
    const int b_u0  = (lane >> 3) & 1;                   // + 2*ks

    int ch[4][4][4], cl[4][4][4];
    #pragma unroll
    for (int i = 0; i < 4; i++)
        #pragma unroll
        for (int j = 0; j < 4; j++)
            #pragma unroll
            for (int r = 0; r < 4; r++) { ch[i][j][r] = 0; cl[i][j][r] = 0; }

    #pragma unroll
    for (int p = 0; p < STAGES - 1; p++) {
        load_stage(sb + p * STAGE_BYTES, tid, p, m0, n0);
        cp_commit();
    }

    #pragma unroll 1
    for (int kt = 0; kt < KT_ITERS; kt++) {
        cp_wait<STAGES - 2>();
        __syncthreads();

        int pk = kt + STAGES - 1;
        if (pk < KT_ITERS)
            load_stage(sb + (pk % STAGES) * STAGE_BYTES, tid, pk, m0, n0);
        cp_commit();

        const uint32_t stg = sb + (kt % STAGES) * STAGE_BYTES;

        #pragma unroll
        for (int ks = 0; ks < 4; ks++) {     // 4 x k32 = BK 128
            uint32_t b[2][4];                // 4 n8-tiles (2 regs each)
            #pragma unroll
            for (int j = 0; j < 2; j++) {
                int r = b_row + j * 16;
                ldsm_x4(b[j], stg + OFF_B + r * 128 +
                        (((uint32_t)((b_u0 + 2 * ks) ^ (r & 7))) << 4));
            }
            uint32_t a[4][4];
            #pragma unroll
            for (int i = 0; i < 4; i++) {    // A_hi fragments
                int r = a_row + i * 16;
                ldsm_x4(a[i], stg + OFF_AH + r * 128 +
                        (((uint32_t)((a_u0 + 2 * ks) ^ (r & 7))) << 4));
            }
            #pragma unroll
            for (int i = 0; i < 4; i++)
                #pragma unroll
                for (int j = 0; j < 2; j++) {
                    imma16832(ch[i][2 * j],     a[i], b[j][0], b[j][1]);
                    imma16832(ch[i][2 * j + 1], a[i], b[j][2], b[j][3]);
                }
            #pragma unroll
            for (int i = 0; i < 4; i++) {    // A_lo fragments (reuse regs)
                int r = a_row + i * 16;
                ldsm_x4(a[i], stg + OFF_AL + r * 128 +
                        (((uint32_t)((a_u0 + 2 * ks) ^ (r & 7))) << 4));
            }
            #pragma unroll
            for (int i = 0; i < 4; i++)
                #pragma unroll
                for (int j = 0; j < 2; j++) {
                    imma16832(cl[i][2 * j],     a[i], b[j][0], b[j][1]);
                    imma16832(cl[i][2 * j + 1], a[i], b[j][2], b[j][3]);
                }
        }
    }
    cp_wait<0>();

    // ---------------- epilogue: s_m * (acc_h + acc_l/256) * ws_n + bias ------
    const int mrow = lane >> 2;
    const int ncol = (lane & 3) * 2;
    #pragma unroll
    for (int j = 0; j < 4; j++) {
        int n = n0 + warp_n * 32 + j * 8 + ncol;
        float2 ws = *reinterpret_cast<const float2*>(scales + n);
        float2 bb = *reinterpret_cast<const float2*>(bias + n);
        #pragma unroll
        for (int i = 0; i < 4; i++) {
            int m = m0 + warp_m * 64 + i * 16 + mrow;
            float sm0 = g_sx[m];
            float sm1 = g_sx[m + 8];
            float a0 = (float)ch[i][j][0] + (float)cl[i][j][0] * (1.0f / 256.0f);
            float a1 = (float)ch[i][j][1] + (float)cl[i][j][1] * (1.0f / 256.0f);
            float a2 = (float)ch[i][j][2] + (float)cl[i][j][2] * (1.0f / 256.0f);
            float a3 = (float)ch[i][j][3] + (float)cl[i][j][3] * (1.0f / 256.0f);
            float2 v0, v1;
            v0.x = a0 * (sm0 * ws.x) + bb.x;
            v0.y = a1 * (sm0 * ws.y) + bb.y;
            v1.x = a2 * (sm1 * ws.x) + bb.x;
            v1.y = a3 * (sm1 * ws.y) + bb.y;
            *reinterpret_cast<float2*>(out + (size_t)m * NDIM + n) = v0;
            *reinterpret_cast<float2*>(out + (size_t)(m + 8) * NDIM + n) = v1;
        }
    }
}

// ---------------- launch ----------------
extern "C" void kernel_launch(void* const* d_in, const int* in_sizes, int n_in,
                              void* d_out, int out_size) {
    const float* x  = (const float*)d_in[0];
    const int*   wp = (const int*)d_in[1];
    const float* sc = (const float*)d_in[2];
    const float* bi = (const float*)d_in[3];
    float* out = (float*)d_out;

    static bool attr_set = false;
    if (!attr_set) {
        cudaFuncSetAttribute(gemm_kernel,
                             cudaFuncAttributeMaxDynamicSharedMemorySize, SMEM_TOTAL);
        attr_set = true;
    }

    prep_kernel<<<QUANT_BLOCKS + UNPACK_BLOCKS, 256>>>(x, wp);
    gemm_kernel<<<(MDIM / BM) * (NDIM / BN), THREADS, SMEM_TOTAL>>>(sc, bi, out);
}

// round 9
// speedup vs baseline: 6.2473x; 6.2473x over previous
#include <cuda_runtime.h>
#include <cuda_fp16.h>
#include <cstdint>

// ---------------- problem dims ----------------
#define MDIM 8192
#define NDIM 4096
#define KDIM 4096

// ---------------- GEMM tiling (best-known: R6 geometry) ----------------
#define BM 128
#define BN 128
#define BK 64                  // 64 fp16 = 128 B per SMEM row
#define STAGES 3
#define KT_ITERS (KDIM / BK)   // 64
#define THREADS 256            // 8 warps: 2 (m) x 4 (n), warp tile 64x32

// SMEM: [0..1024) barriers, then 3 stages x (A 16KB | B 16KB)
#define SM_FULL(s)   ((s) * 8)
#define SM_EMPTY(s)  (64 + (s) * 8)
#define SM_TILE0     1024
#define OFF_A 0
#define OFF_B 16384
#define STAGE_BYTES 32768
#define SMEM_TOTAL (SM_TILE0 + STAGES * STAGE_BYTES)   // 99328 -> 2 CTAs/SM

#define PREP_BLOCKS_W (NDIM * (KDIM / 2) / 256)   // 32768
#define PREP_BLOCKS_X (MDIM * (KDIM / 4) / 256)   // 32768

// ---------------- scratch (allocation-free __device__ globals) ----------------
__device__ __half g_A [(size_t)MDIM * KDIM];   // 64 MB fp16 activations
__device__ __half g_Bw[(size_t)NDIM * KDIM];   // 32 MB fp16 unpacked weights

// ---------------- PTX helpers ----------------
__device__ __forceinline__ uint32_t smem_u32(const void* p) {
    return (uint32_t)__cvta_generic_to_shared(p);
}
__device__ __forceinline__ void cp16(uint32_t s, const void* g) {
    asm volatile("cp.async.cg.shared.global [%0], [%1], 16;" :: "r"(s), "l"(g));
}
__device__ __forceinline__ void mbar_init(uint32_t a, uint32_t cnt) {
    asm volatile("mbarrier.init.shared.b64 [%0], %1;" :: "r"(a), "r"(cnt) : "memory");
}
__device__ __forceinline__ void mbar_arrive(uint32_t a) {
    asm volatile("mbarrier.arrive.shared.b64 _, [%0];" :: "r"(a) : "memory");
}
__device__ __forceinline__ void cp_arrive_noinc(uint32_t a) {
    asm volatile("cp.async.mbarrier.arrive.noinc.shared::cta.b64 [%0];"
                 :: "r"(a) : "memory");
}
__device__ __forceinline__ void mbar_wait(uint32_t mbar, uint32_t parity) {
    asm volatile(
        "{\n\t.reg .pred P;\n\t"
        "WL%=:\n\t"
        "mbarrier.try_wait.parity.acquire.cta.shared::cta.b64 P, [%0], %1, 0x989680;\n\t"
        "@P bra.uni WD%=;\n\t"
        "bra.uni WL%=;\n\t"
        "WD%=:\n\t}"
        :: "r"(mbar), "r"(parity) : "memory");
}
__device__ __forceinline__ void ldsm_x4(uint32_t* d, uint32_t addr) {
    asm volatile("ldmatrix.sync.aligned.m8n8.x4.shared.b16 {%0,%1,%2,%3}, [%4];"
                 : "=r"(d[0]), "=r"(d[1]), "=r"(d[2]), "=r"(d[3]) : "r"(addr));
}
__device__ __forceinline__ void mma16816(float* c, const uint32_t* a,
                                         uint32_t b0, uint32_t b1) {
    asm volatile(
        "mma.sync.aligned.m16n8k16.row.col.f32.f16.f16.f32 "
        "{%0,%1,%2,%3}, {%4,%5,%6,%7}, {%8,%9}, {%0,%1,%2,%3};"
        : "+f"(c[0]), "+f"(c[1]), "+f"(c[2]), "+f"(c[3])
        : "r"(a[0]), "r"(a[1]), "r"(a[2]), "r"(a[3]), "r"(b0), "r"(b1));
}

// ---------------- merged prep: unpack weights + convert activations ----------------
__global__ __launch_bounds__(256) void prep_kernel(const int* __restrict__ wp,
                                                   const float4* __restrict__ x4) {
    int bid = blockIdx.x;
    if (bid < PREP_BLOCKS_W) {
        int idx = bid * 256 + threadIdx.x;        // 0 .. N*K/2-1
        int v = wp[idx];
        float lo = (float)((v & 0xF) - 8);        // XOR 0x88 + sext == nibble-8
        float hi = (float)(((v >> 4) & 0xF) - 8);
        reinterpret_cast<__half2*>(g_Bw)[idx] = __floats2half2_rn(lo, hi);
    } else {
        int idx = (bid - PREP_BLOCKS_W) * 256 + threadIdx.x;   // 0 .. M*K/4-1
        float4 v = x4[idx];
        __half2 h0 = __floats2half2_rn(v.x, v.y);
        __half2 h1 = __floats2half2_rn(v.z, v.w);
        __half2* H = reinterpret_cast<__half2*>(g_A);
        H[2 * idx]     = h0;
        H[2 * idx + 1] = h1;
    }
}

// ---------------- stage loader: A 1024 + B 1024 chunks of 16B ----------------
__device__ __forceinline__ void load_stage(uint32_t sbase, int tid, int kt,
                                           int m0, int n0) {
    const char* ga = (const char*)(g_A  + (size_t)m0 * KDIM + kt * BK);
    const char* gb = (const char*)(g_Bw + (size_t)n0 * KDIM + kt * BK);
    #pragma unroll
    for (int j = 0; j < 4; j++) {          // A: 128 rows x 8 units
        int c = tid + j * THREADS;
        int row = c >> 3, u = c & 7;
        uint32_t sa = sbase + OFF_A + row * 128 + (((uint32_t)(u ^ (row & 7))) << 4);
        cp16(sa, ga + (size_t)row * (KDIM * 2) + u * 16);
    }
    #pragma unroll
    for (int j = 0; j < 4; j++) {          // B: 128 rows x 8 units
        int c = tid + j * THREADS;
        int row = c >> 3, u = c & 7;
        uint32_t sa = sbase + OFF_B + row * 128 + (((uint32_t)(u ^ (row & 7))) << 4);
        cp16(sa, gb + (size_t)row * (KDIM * 2) + u * 16);
    }
}

// ---------------- kernel: fp16 mma.sync GEMM, mbarrier ring pipeline ----------------
__global__ __launch_bounds__(THREADS, 2) void gemm_kernel(
    const float* __restrict__ scales, const float* __restrict__ bias,
    float* __restrict__ out)
{
    extern __shared__ char smem[];
    const uint32_t sb = smem_u32(smem);
    const int tid = threadIdx.x;
    const int wid = tid >> 5;
    const int lane = tid & 31;

    const int tn = blockIdx.x & 31;   // 32 N-tiles (fastest -> A reuse in L2)
    const int tm = blockIdx.x >> 5;   // 64 M-tiles
    const int m0 = tm * BM;
    const int n0 = tn * BN;

    const int warp_m = wid & 1;       // 2 groups of 64 rows
    const int warp_n = wid >> 1;      // 4 groups of 32 cols

    // per-lane ldmatrix addressing (swizzled: unit16 u ^ (row & 7))
    const int a_row = warp_m * 64 + (lane & 15);
    const int a_u0  = lane >> 4;                         // + 2*ks
    const int b_row = warp_n * 32 + (lane & 7) + ((lane >> 4) << 3);
    const int b_u0  = (lane >> 3) & 1;                   // + 2*ks

    if (tid == 0) {
        #pragma unroll
        for (int s = 0; s < STAGES; s++) {
            mbar_init(sb + SM_FULL(s), THREADS);   // 256 cp.async completions
            mbar_init(sb + SM_EMPTY(s), 8);        // 8 warps release
        }
    }
    __syncthreads();   // barriers visible before any arrive

    float c[4][4][4];
    #pragma unroll
    for (int i = 0; i < 4; i++)
        #pragma unroll
        for (int j = 0; j < 4; j++)
            #pragma unroll
            for (int r = 0; r < 4; r++) c[i][j][r] = 0.0f;

    // prologue: fill stages 0,1 (fresh empty barriers -> no wait needed)
    #pragma unroll
    for (int p = 0; p < STAGES - 1; p++) {
        load_stage(sb + SM_TILE0 + p * STAGE_BYTES, tid, p, m0, n0);
        cp_arrive_noinc(sb + SM_FULL(p));
    }

    // cursors: consumer (stage 0, phase 0); producer (stage 2, phase 1)
    int cs = 0, cph = 0;
    int ps = STAGES - 1, pph = 1;

    #pragma unroll 1
    for (int kt = 0; kt < KT_ITERS; kt++) {
        mbar_wait(sb + SM_FULL(cs), (uint32_t)cph);
        const uint32_t stg = sb + SM_TILE0 + cs * STAGE_BYTES;
        const uint32_t sA  = stg + OFF_A;
        const uint32_t sBm = stg + OFF_B;

        #pragma unroll
        for (int ks = 0; ks < 4; ks++) {
            uint32_t a[4][4], b[2][4];
            #pragma unroll
            for (int i = 0; i < 4; i++) {
                int r = a_row + i * 16;
                ldsm_x4(a[i], sA + r * 128 +
                        (((uint32_t)((a_u0 + 2 * ks) ^ (r & 7))) << 4));
            }
            #pragma unroll
            for (int j = 0; j < 2; j++) {
                int r = b_row + j * 16;
                ldsm_x4(b[j], sBm + r * 128 +
                        (((uint32_t)((b_u0 + 2 * ks) ^ (r & 7))) << 4));
            }
            #pragma unroll
            for (int i = 0; i < 4; i++) {
                #pragma unroll
                for (int j = 0; j < 2; j++) {
                    mma16816(c[i][2 * j],     a[i], b[j][0], b[j][1]);
                    mma16816(c[i][2 * j + 1], a[i], b[j][2], b[j][3]);
                }
            }
        }
        // this warp is done reading stage cs
        if (lane == 0) mbar_arrive(sb + SM_EMPTY(cs));

        // produce stage for kt + STAGES - 1
        int pk = kt + STAGES - 1;
        if (pk < KT_ITERS) {
            mbar_wait(sb + SM_EMPTY(ps), (uint32_t)pph);
            load_stage(sb + SM_TILE0 + ps * STAGE_BYTES, tid, pk, m0, n0);
            cp_arrive_noinc(sb + SM_FULL(ps));
            if (++ps == STAGES) { ps = 0; pph ^= 1; }
        }
        if (++cs == STAGES) { cs = 0; cph ^= 1; }
    }

    // ---------------- epilogue (per-warp, no block sync): scale*acc + bias ----
    const int mrow = lane >> 2;
    const int ncol = (lane & 3) * 2;
    #pragma unroll
    for (int j = 0; j < 4; j++) {
        int n = n0 + warp_n * 32 + j * 8 + ncol;
        float2 s  = *reinterpret_cast<const float2*>(scales + n);
        float2 bb = *reinterpret_cast<const float2*>(bias + n);
        #pragma unroll
        for (int i = 0; i < 4; i++) {
            int m = m0 + warp_m * 64 + i * 16 + mrow;
            float2 v0, v1;
            v0.x = c[i][j][0] * s.x + bb.x;
            v0.y = c[i][j][1] * s.y + bb.y;
            v1.x = c[i][j][2] * s.x + bb.x;
            v1.y = c[i][j][3] * s.y + bb.y;
            *reinterpret_cast<float2*>(out + (size_t)m * NDIM + n) = v0;
            *reinterpret_cast<float2*>(out + (size_t)(m + 8) * NDIM + n) = v1;
        }
    }
}

// ---------------- launch ----------------
extern "C" void kernel_launch(void* const* d_in, const int* in_sizes, int n_in,
                              void* d_out, int out_size) {
    const float* x  = (const float*)d_in[0];
    const int*   wp = (const int*)d_in[1];
    const float* sc = (const float*)d_in[2];
    const float* bi = (const float*)d_in[3];
    float* out = (float*)d_out;

    static bool attr_set = false;
    if (!attr_set) {
        cudaFuncSetAttribute(gemm_kernel,
                             cudaFuncAttributeMaxDynamicSharedMemorySize, SMEM_TOTAL);
        attr_set = true;
    }

    prep_kernel<<<PREP_BLOCKS_W + PREP_BLOCKS_X, 256>>>(wp, (const float4*)x);
    gemm_kernel<<<(MDIM / BM) * (NDIM / BN), THREADS, SMEM_TOTAL>>>(sc, bi, out);
}

// round 10
// speedup vs baseline: 6.4863x; 1.0383x over previous
#include <cuda_runtime.h>
#include <cuda_fp16.h>
#include <cstdint>

// ---------------- problem dims ----------------
#define MDIM 8192
#define NDIM 4096
#define KDIM 4096

// ---------------- GEMM tiling ----------------
#define BM 128
#define BN 128
#define BK 64                  // 64 fp16 = 128 B per SMEM row
#define STAGES 3
#define KT_ITERS (KDIM / BK)   // 64
#define THREADS 128            // 4 warps: 2 (m) x 2 (n), warp tile 64x64

// SMEM: [0..1024) barriers, then 3 stages x (A 16KB | B 16KB)
#define SM_FULL(s)   ((s) * 8)
#define SM_EMPTY(s)  (64 + (s) * 8)
#define SM_TILE0     1024
#define OFF_A 0
#define OFF_B 16384
#define STAGE_BYTES 32768
#define SMEM_TOTAL (SM_TILE0 + STAGES * STAGE_BYTES)   // 99328 -> 2 CTAs/SM

#define PREP_BLOCKS_W (NDIM * (KDIM / 2) / 256)   // 32768
#define PREP_BLOCKS_X (MDIM * (KDIM / 4) / 256)   // 32768

// ---------------- scratch (allocation-free __device__ globals) ----------------
__device__ __half g_A [(size_t)MDIM * KDIM];   // 64 MB fp16 activations
__device__ __half g_Bw[(size_t)NDIM * KDIM];   // 32 MB fp16 unpacked weights

// ---------------- PTX helpers ----------------
__device__ __forceinline__ uint32_t smem_u32(const void* p) {
    return (uint32_t)__cvta_generic_to_shared(p);
}
__device__ __forceinline__ void cp16(uint32_t s, const void* g) {
    asm volatile("cp.async.cg.shared.global [%0], [%1], 16;" :: "r"(s), "l"(g));
}
__device__ __forceinline__ void mbar_init(uint32_t a, uint32_t cnt) {
    asm volatile("mbarrier.init.shared.b64 [%0], %1;" :: "r"(a), "r"(cnt) : "memory");
}
__device__ __forceinline__ void mbar_arrive(uint32_t a) {
    asm volatile("mbarrier.arrive.shared.b64 _, [%0];" :: "r"(a) : "memory");
}
__device__ __forceinline__ void cp_arrive_noinc(uint32_t a) {
    asm volatile("cp.async.mbarrier.arrive.noinc.shared::cta.b64 [%0];"
                 :: "r"(a) : "memory");
}
__device__ __forceinline__ void mbar_wait(uint32_t mbar, uint32_t parity) {
    asm volatile(
        "{\n\t.reg .pred P;\n\t"
        "WL%=:\n\t"
        "mbarrier.try_wait.parity.acquire.cta.shared::cta.b64 P, [%0], %1, 0x989680;\n\t"
        "@P bra.uni WD%=;\n\t"
        "bra.uni WL%=;\n\t"
        "WD%=:\n\t}"
        :: "r"(mbar), "r"(parity) : "memory");
}
__device__ __forceinline__ void ldsm_x4(uint32_t* d, uint32_t addr) {
    asm volatile("ldmatrix.sync.aligned.m8n8.x4.shared.b16 {%0,%1,%2,%3}, [%4];"
                 : "=r"(d[0]), "=r"(d[1]), "=r"(d[2]), "=r"(d[3]) : "r"(addr));
}
__device__ __forceinline__ void mma16816(float* c, const uint32_t* a,
                                         uint32_t b0, uint32_t b1) {
    asm volatile(
        "mma.sync.aligned.m16n8k16.row.col.f32.f16.f16.f32 "
        "{%0,%1,%2,%3}, {%4,%5,%6,%7}, {%8,%9}, {%0,%1,%2,%3};"
        : "+f"(c[0]), "+f"(c[1]), "+f"(c[2]), "+f"(c[3])
        : "r"(a[0]), "r"(a[1]), "r"(a[2]), "r"(a[3]), "r"(b0), "r"(b1));
}

// ---------------- merged prep: unpack weights + convert activations ----------------
__global__ __launch_bounds__(256) void prep_kernel(const int* __restrict__ wp,
                                                   const float4* __restrict__ x4) {
    int bid = blockIdx.x;
    if (bid < PREP_BLOCKS_W) {
        int idx = bid * 256 + threadIdx.x;        // 0 .. N*K/2-1
        int v = wp[idx];
        float lo = (float)((v & 0xF) - 8);        // XOR 0x88 + sext == nibble-8
        float hi = (float)(((v >> 4) & 0xF) - 8);
        reinterpret_cast<__half2*>(g_Bw)[idx] = __floats2half2_rn(lo, hi);
    } else {
        int idx = (bid - PREP_BLOCKS_W) * 256 + threadIdx.x;   // 0 .. M*K/4-1
        float4 v = x4[idx];
        __half2 h0 = __floats2half2_rn(v.x, v.y);
        __half2 h1 = __floats2half2_rn(v.z, v.w);
        __half2* H = reinterpret_cast<__half2*>(g_A);
        H[2 * idx]     = h0;
        H[2 * idx + 1] = h1;
    }
}

// ---------------- stage loader: A 1024 + B 1024 chunks of 16B (128 thr) --------
__device__ __forceinline__ void load_stage(uint32_t sbase, int tid, int kt,
                                           int m0, int n0) {
    const char* ga = (const char*)(g_A  + (size_t)m0 * KDIM + kt * BK);
    const char* gb = (const char*)(g_Bw + (size_t)n0 * KDIM + kt * BK);
    #pragma unroll
    for (int j = 0; j < 8; j++) {          // A: 128 rows x 8 units
        int c = tid + j * THREADS;
        int row = c >> 3, u = c & 7;
        uint32_t sa = sbase + OFF_A + row * 128 + (((uint32_t)(u ^ (row & 7))) << 4);
        cp16(sa, ga + (size_t)row * (KDIM * 2) + u * 16);
    }
    #pragma unroll
    for (int j = 0; j < 8; j++) {          // B: 128 rows x 8 units
        int c = tid + j * THREADS;
        int row = c >> 3, u = c & 7;
        uint32_t sa = sbase + OFF_B + row * 128 + (((uint32_t)(u ^ (row & 7))) << 4);
        cp16(sa, gb + (size_t)row * (KDIM * 2) + u * 16);
    }
}

// ---------------- kernel: fp16 mma.sync GEMM, mbarrier ring, 64x64 warps -------
__global__ __launch_bounds__(THREADS, 2) void gemm_kernel(
    const float* __restrict__ scales, const float* __restrict__ bias,
    float* __restrict__ out)
{
    extern __shared__ char smem[];
    const uint32_t sb = smem_u32(smem);
    const int tid = threadIdx.x;
    const int wid = tid >> 5;
    const int lane = tid & 31;

    const int tn = blockIdx.x & 31;   // 32 N-tiles (fastest -> A reuse in L2)
    const int tm = blockIdx.x >> 5;   // 64 M-tiles
    const int m0 = tm * BM;
    const int n0 = tn * BN;

    const int warp_m = wid & 1;       // 2 groups of 64 rows
    const int warp_n = wid >> 1;      // 2 groups of 64 cols

    // per-lane ldmatrix addressing (swizzled: unit16 u ^ (row & 7))
    const int a_row = warp_m * 64 + (lane & 15);
    const int a_u0  = lane >> 4;                         // + 2*ks
    const int b_row = warp_n * 64 + (lane & 7) + ((lane >> 4) << 3);
    const int b_u0  = (lane >> 3) & 1;                   // + 2*ks

    if (tid == 0) {
        #pragma unroll
        for (int s = 0; s < STAGES; s++) {
            mbar_init(sb + SM_FULL(s), THREADS);   // 128 cp.async completions
            mbar_init(sb + SM_EMPTY(s), 4);        // 4 warps release
        }
    }
    __syncthreads();   // barriers visible before any arrive

    float c[4][8][4];
    #pragma unroll
    for (int i = 0; i < 4; i++)
        #pragma unroll
        for (int j = 0; j < 8; j++)
            #pragma unroll
            for (int r = 0; r < 4; r++) c[i][j][r] = 0.0f;

    // prologue: fill stages 0,1 (fresh empty barriers -> no wait needed)
    #pragma unroll
    for (int p = 0; p < STAGES - 1; p++) {
        load_stage(sb + SM_TILE0 + p * STAGE_BYTES, tid, p, m0, n0);
        cp_arrive_noinc(sb + SM_FULL(p));
    }

    // cursors: consumer (stage 0, phase 0); producer (stage 2, phase 1)
    int cs = 0, cph = 0;
    int ps = STAGES - 1, pph = 1;

    #pragma unroll 1
    for (int kt = 0; kt < KT_ITERS; kt++) {
        mbar_wait(sb + SM_FULL(cs), (uint32_t)cph);
        const uint32_t stg = sb + SM_TILE0 + cs * STAGE_BYTES;
        const uint32_t sA  = stg + OFF_A;
        const uint32_t sBm = stg + OFF_B;

        #pragma unroll
        for (int ks = 0; ks < 4; ks++) {
            uint32_t a[4][4], b[4][4];
            #pragma unroll
            for (int i = 0; i < 4; i++) {
                int r = a_row + i * 16;
                ldsm_x4(a[i], sA + r * 128 +
                        (((uint32_t)((a_u0 + 2 * ks) ^ (r & 7))) << 4));
            }
            #pragma unroll
            for (int j = 0; j < 4; j++) {
                int r = b_row + j * 16;
                ldsm_x4(b[j], sBm + r * 128 +
                        (((uint32_t)((b_u0 + 2 * ks) ^ (r & 7))) << 4));
            }
            #pragma unroll
            for (int i = 0; i < 4; i++) {
                #pragma unroll
                for (int j = 0; j < 4; j++) {
                    mma16816(c[i][2 * j],     a[i], b[j][0], b[j][1]);
                    mma16816(c[i][2 * j + 1], a[i], b[j][2], b[j][3]);
                }
            }
        }
        // this warp is done reading stage cs
        if (lane == 0) mbar_arrive(sb + SM_EMPTY(cs));

        // produce stage for kt + STAGES - 1
        int pk = kt + STAGES - 1;
        if (pk < KT_ITERS) {
            mbar_wait(sb + SM_EMPTY(ps), (uint32_t)pph);
            load_stage(sb + SM_TILE0 + ps * STAGE_BYTES, tid, pk, m0, n0);
            cp_arrive_noinc(sb + SM_FULL(ps));
            if (++ps == STAGES) { ps = 0; pph ^= 1; }
        }
        if (++cs == STAGES) { cs = 0; cph ^= 1; }
    }

    // ---------------- epilogue (per-warp, no block sync): scale*acc + bias ----
    const int mrow = lane >> 2;
    const int ncol = (lane & 3) * 2;
    #pragma unroll
    for (int j = 0; j < 8; j++) {
        int n = n0 + warp_n * 64 + j * 8 + ncol;
        float2 s  = *reinterpret_cast<const float2*>(scales + n);
        float2 bb = *reinterpret_cast<const float2*>(bias + n);
        #pragma unroll
        for (int i = 0; i < 4; i++) {
            int m = m0 + warp_m * 64 + i * 16 + mrow;
            float2 v0, v1;
            v0.x = c[i][j][0] * s.x + bb.x;
            v0.y = c[i][j][1] * s.y + bb.y;
            v1.x = c[i][j][2] * s.x + bb.x;
            v1.y = c[i][j][3] * s.y + bb.y;
            *reinterpret_cast<float2*>(out + (size_t)m * NDIM + n) = v0;
            *reinterpret_cast<float2*>(out + (size_t)(m + 8) * NDIM + n) = v1;
        }
    }
}

// ---------------- launch ----------------
extern "C" void kernel_launch(void* const* d_in, const int* in_sizes, int n_in,
                              void* d_out, int out_size) {
    const float* x  = (const float*)d_in[0];
    const int*   wp = (const int*)d_in[1];
    const float* sc = (const float*)d_in[2];
    const float* bi = (const float*)d_in[3];
    float* out = (float*)d_out;

    static bool attr_set = false;
    if (!attr_set) {
        cudaFuncSetAttribute(gemm_kernel,
                             cudaFuncAttributeMaxDynamicSharedMemorySize, SMEM_TOTAL);
        attr_set = true;
    }

    prep_kernel<<<PREP_BLOCKS_W + PREP_BLOCKS_X, 256>>>(wp, (const float4*)x);
    gemm_kernel<<<(MDIM / BM) * (NDIM / BN), THREADS, SMEM_TOTAL>>>(sc, bi, out);
}

// round 11
// speedup vs baseline: 6.9415x; 1.0702x over previous
#include <cuda_runtime.h>
#include <cuda_fp16.h>
#include <cstdint>

// ---------------- problem dims ----------------
#define MDIM 8192
#define NDIM 4096
#define KDIM 4096

// ---------------- GEMM tiling ----------------
#define BM 128
#define BN 128
#define BK 64                  // 64 fp16 = 128 B per row; tile = 16 KB
#define STAGES 3
#define KT_ITERS (KDIM / BK)   // 64
#define THREADS 128            // 4 warps: 2 (m) x 2 (n), warp tile 64x64
#define TILE_BYTES 16384

// SMEM: [0..1024) barriers, then 3 stages x (A 16KB | B 16KB)
#define SM_FULL(s)   ((s) * 8)
#define SM_EMPTY(s)  (64 + (s) * 8)
#define SM_TILE0     1024
#define OFF_A 0
#define OFF_B 16384
#define STAGE_BYTES 32768
#define SMEM_TOTAL (SM_TILE0 + STAGES * STAGE_BYTES)   // 99328 -> 2 CTAs/SM

// prep: one 16B unit (8 fp16) per thread
#define W_UNITS (NDIM * KDIM / 8)       // 2M
#define X_UNITS (MDIM * KDIM / 8)       // 4M
#define W_BLOCKS (W_UNITS / 256)        // 8192
#define X_BLOCKS (X_UNITS / 256)        // 16384

// ---------------- scratch: pre-swizzled 16KB-tiled layouts ----------------
// g_A: [tm (64)][kt (64)] tiles; tile = 128 rows x 128B, unit u at u^(row&7)
// g_Bw: [tn (32)][kt (64)] tiles; same form
__device__ __align__(256) char g_A [(size_t)MDIM * KDIM * 2];   // 64 MB
__device__ __align__(256) char g_Bw[(size_t)NDIM * KDIM * 2];   // 32 MB

// ---------------- PTX helpers ----------------
__device__ __forceinline__ uint32_t smem_u32(const void* p) {
    return (uint32_t)__cvta_generic_to_shared(p);
}
__device__ __forceinline__ void mbar_init(uint32_t a, uint32_t cnt) {
    asm volatile("mbarrier.init.shared.b64 [%0], %1;" :: "r"(a), "r"(cnt) : "memory");
}
__device__ __forceinline__ void mbar_arrive(uint32_t a) {
    asm volatile("mbarrier.arrive.shared.b64 _, [%0];" :: "r"(a) : "memory");
}
__device__ __forceinline__ void mbar_expect_tx(uint32_t a, uint32_t bytes) {
    asm volatile("mbarrier.arrive.expect_tx.shared.b64 _, [%0], %1;"
                 :: "r"(a), "r"(bytes) : "memory");
}
__device__ __forceinline__ void bulk_g2s(uint32_t dst, const void* src,
                                         uint32_t bytes, uint32_t mbar) {
    asm volatile(
        "cp.async.bulk.shared::cluster.global.mbarrier::complete_tx::bytes "
        "[%0], [%1], %2, [%3];"
        :: "r"(dst), "l"(src), "r"(bytes), "r"(mbar) : "memory");
}
__device__ __forceinline__ void mbar_wait(uint32_t mbar, uint32_t parity) {
    asm volatile(
        "{\n\t.reg .pred P;\n\t"
        "WL%=:\n\t"
        "mbarrier.try_wait.parity.acquire.cta.shared::cta.b64 P, [%0], %1, 0x989680;\n\t"
        "@P bra.uni WD%=;\n\t"
        "bra.uni WL%=;\n\t"
        "WD%=:\n\t}"
        :: "r"(mbar), "r"(parity) : "memory");
}
__device__ __forceinline__ void ldsm_x4(uint32_t* d, uint32_t addr) {
    asm volatile("ldmatrix.sync.aligned.m8n8.x4.shared.b16 {%0,%1,%2,%3}, [%4];"
                 : "=r"(d[0]), "=r"(d[1]), "=r"(d[2]), "=r"(d[3]) : "r"(addr));
}
__device__ __forceinline__ void mma16816(float* c, const uint32_t* a,
                                         uint32_t b0, uint32_t b1) {
    asm volatile(
        "mma.sync.aligned.m16n8k16.row.col.f32.f16.f16.f32 "
        "{%0,%1,%2,%3}, {%4,%5,%6,%7}, {%8,%9}, {%0,%1,%2,%3};"
        : "+f"(c[0]), "+f"(c[1]), "+f"(c[2]), "+f"(c[3])
        : "r"(a[0]), "r"(a[1]), "r"(a[2]), "r"(a[3]), "r"(b0), "r"(b1));
}

// ---------------- prep: emit pre-swizzled 16KB tiles ----------------
// blocks [0, W_BLOCKS): weights. unit = 4 int32 (one byte each) -> 8 fp16 = 16B
// blocks [W_BLOCKS, +X_BLOCKS): activations. unit = 8 floats -> 8 fp16 = 16B
__global__ __launch_bounds__(256) void prep_kernel(const int* __restrict__ wp,
                                                   const float4* __restrict__ x4) {
    int bid = blockIdx.x;
    if (bid < W_BLOCKS) {
        int wu = bid * 256 + threadIdx.x;      // 0 .. W_UNITS-1
        int n  = wu >> 9;                      // 512 units per row (K/8)
        int ku = wu & 511;
        int4 p = reinterpret_cast<const int4*>(wp)[wu];   // 4 int32, contiguous
        __half2 h[4];
        h[0] = __floats2half2_rn((float)((p.x & 0xF) - 8),
                                 (float)(((p.x >> 4) & 0xF) - 8));
        h[1] = __floats2half2_rn((float)((p.y & 0xF) - 8),
                                 (float)(((p.y >> 4) & 0xF) - 8));
        h[2] = __floats2half2_rn((float)((p.z & 0xF) - 8),
                                 (float)(((p.z >> 4) & 0xF) - 8));
        h[3] = __floats2half2_rn((float)((p.w & 0xF) - 8),
                                 (float)(((p.w >> 4) & 0xF) - 8));
        int tn = n >> 7, row = n & 127, kt = ku >> 3, u = ku & 7;
        size_t dst = ((size_t)(tn * KT_ITERS + kt) << 14)
                   + row * 128 + ((u ^ (row & 7)) << 4);
        *reinterpret_cast<uint4*>(g_Bw + dst) = *reinterpret_cast<uint4*>(h);
    } else {
        int xu = (bid - W_BLOCKS) * 256 + threadIdx.x;    // 0 .. X_UNITS-1
        int m  = xu >> 9;
        int ku = xu & 511;
        float4 v0 = x4[2 * xu], v1 = x4[2 * xu + 1];
        __half2 h[4];
        h[0] = __floats2half2_rn(v0.x, v0.y);
        h[1] = __floats2half2_rn(v0.z, v0.w);
        h[2] = __floats2half2_rn(v1.x, v1.y);
        h[3] = __floats2half2_rn(v1.z, v1.w);
        int tm = m >> 7, row = m & 127, kt = ku >> 3, u = ku & 7;
        size_t dst = ((size_t)(tm * KT_ITERS + kt) << 14)
                   + row * 128 + ((u ^ (row & 7)) << 4);
        *reinterpret_cast<uint4*>(g_A + dst) = *reinterpret_cast<uint4*>(h);
    }
}

// ---------------- kernel: fp16 mma.sync GEMM, TMA-bulk mbarrier ring ----------
__global__ __launch_bounds__(THREADS, 2) void gemm_kernel(
    const float* __restrict__ scales, const float* __restrict__ bias,
    float* __restrict__ out)
{
    extern __shared__ char smem[];
    const uint32_t sb = smem_u32(smem);
    const int tid = threadIdx.x;
    const int wid = tid >> 5;
    const int lane = tid & 31;

    const int tn = blockIdx.x & 31;   // 32 N-tiles (fastest -> A reuse in L2)
    const int tm = blockIdx.x >> 5;   // 64 M-tiles
    const int m0 = tm * BM;
    const int n0 = tn * BN;

    const char* gA = g_A  + ((size_t)tm * KT_ITERS << 14);
    const char* gB = g_Bw + ((size_t)tn * KT_ITERS << 14);

    const int warp_m = wid & 1;       // 2 groups of 64 rows
    const int warp_n = wid >> 1;      // 2 groups of 64 cols

    // per-lane ldmatrix addressing (swizzled: unit16 u ^ (row & 7))
    const int a_row = warp_m * 64 + (lane & 15);
    const int a_u0  = lane >> 4;                         // + 2*ks
    const int b_row = warp_n * 64 + (lane & 7) + ((lane >> 4) << 3);
    const int b_u0  = (lane >> 3) & 1;                   // + 2*ks

    if (tid == 0) {
        #pragma unroll
        for (int s = 0; s < STAGES; s++) {
            mbar_init(sb + SM_FULL(s), 1);     // one expect_tx producer
            mbar_init(sb + SM_EMPTY(s), 4);    // 4 warps release
        }
    }
    __syncthreads();   // barriers visible before any arrive / bulk

    float c[4][8][4];
    #pragma unroll
    for (int i = 0; i < 4; i++)
        #pragma unroll
        for (int j = 0; j < 8; j++)
            #pragma unroll
            for (int r = 0; r < 4; r++) c[i][j][r] = 0.0f;

    // prologue: tid0 issues bulk copies for stages 0,1
    if (tid == 0) {
        #pragma unroll
        for (int p = 0; p < STAGES - 1; p++) {
            uint32_t stg = sb + SM_TILE0 + p * STAGE_BYTES;
            mbar_expect_tx(sb + SM_FULL(p), STAGE_BYTES);
            bulk_g2s(stg + OFF_A, gA + ((size_t)p << 14), TILE_BYTES,
                     sb + SM_FULL(p));
            bulk_g2s(stg + OFF_B, gB + ((size_t)p << 14), TILE_BYTES,
                     sb + SM_FULL(p));
        }
    }

    // cursors: consumer (stage 0, phase 0); producer (stage 2, phase 1)
    int cs = 0, cph = 0;
    int ps = STAGES - 1, pph = 1;

    #pragma unroll 1
    for (int kt = 0; kt < KT_ITERS; kt++) {
        mbar_wait(sb + SM_FULL(cs), (uint32_t)cph);
        const uint32_t stg = sb + SM_TILE0 + cs * STAGE_BYTES;
        const uint32_t sA  = stg + OFF_A;
        const uint32_t sBm = stg + OFF_B;

        #pragma unroll
        for (int ks = 0; ks < 4; ks++) {
            uint32_t a[4][4], b[4][4];
            #pragma unroll
            for (int i = 0; i < 4; i++) {
                int r = a_row + i * 16;
                ldsm_x4(a[i], sA + r * 128 +
                        (((uint32_t)((a_u0 + 2 * ks) ^ (r & 7))) << 4));
            }
            #pragma unroll
            for (int j = 0; j < 4; j++) {
                int r = b_row + j * 16;
                ldsm_x4(b[j], sBm + r * 128 +
                        (((uint32_t)((b_u0 + 2 * ks) ^ (r & 7))) << 4));
            }
            #pragma unroll
            for (int i = 0; i < 4; i++) {
                #pragma unroll
                for (int j = 0; j < 4; j++) {
                    mma16816(c[i][2 * j],     a[i], b[j][0], b[j][1]);
                    mma16816(c[i][2 * j + 1], a[i], b[j][2], b[j][3]);
                }
            }
        }
        // this warp is done reading stage cs
        if (lane == 0) mbar_arrive(sb + SM_EMPTY(cs));

        // produce stage for kt + STAGES - 1 (tid0 only; bulk = async proxy)
        int pk = kt + STAGES - 1;
        if (pk < KT_ITERS) {
            if (tid == 0) {
                mbar_wait(sb + SM_EMPTY(ps), (uint32_t)pph);
                uint32_t pstg = sb + SM_TILE0 + ps * STAGE_BYTES;
                mbar_expect_tx(sb + SM_FULL(ps), STAGE_BYTES);
                bulk_g2s(pstg + OFF_A, gA + ((size_t)pk << 14), TILE_BYTES,
                         sb + SM_FULL(ps));
                bulk_g2s(pstg + OFF_B, gB + ((size_t)pk << 14), TILE_BYTES,
                         sb + SM_FULL(ps));
            }
            if (++ps == STAGES) { ps = 0; pph ^= 1; }
        }
        if (++cs == STAGES) { cs = 0; cph ^= 1; }
    }

    // ---------------- epilogue (per-warp, no block sync): scale*acc + bias ----
    const int mrow = lane >> 2;
    const int ncol = (lane & 3) * 2;
    #pragma unroll
    for (int j = 0; j < 8; j++) {
        int n = n0 + warp_n * 64 + j * 8 + ncol;
        float2 s  = *reinterpret_cast<const float2*>(scales + n);
        float2 bb = *reinterpret_cast<const float2*>(bias + n);
        #pragma unroll
        for (int i = 0; i < 4; i++) {
            int m = m0 + warp_m * 64 + i * 16 + mrow;
            float2 v0, v1;
            v0.x = c[i][j][0] * s.x + bb.x;
            v0.y = c[i][j][1] * s.y + bb.y;
            v1.x = c[i][j][2] * s.x + bb.x;
            v1.y = c[i][j][3] * s.y + bb.y;
            *reinterpret_cast<float2*>(out + (size_t)m * NDIM + n) = v0;
            *reinterpret_cast<float2*>(out + (size_t)(m + 8) * NDIM + n) = v1;
        }
    }
}

// ---------------- launch ----------------
extern "C" void kernel_launch(void* const* d_in, const int* in_sizes, int n_in,
                              void* d_out, int out_size) {
    const float* x  = (const float*)d_in[0];
    const int*   wp = (const int*)d_in[1];
    const float* sc = (const float*)d_in[2];
    const float* bi = (const float*)d_in[3];
    float* out = (float*)d_out;

    static bool attr_set = false;
    if (!attr_set) {
        cudaFuncSetAttribute(gemm_kernel,
                             cudaFuncAttributeMaxDynamicSharedMemorySize, SMEM_TOTAL);
        attr_set = true;
    }

    prep_kernel<<<W_BLOCKS + X_BLOCKS, 256>>>(wp, (const float4*)x);
    gemm_kernel<<<(MDIM / BM) * (NDIM / BN), THREADS, SMEM_TOTAL>>>(sc, bi, out);
}